// round 15
// baseline (speedup 1.0000x reference)
#include <cuda_runtime.h>

// ---------------- problem constants ----------------
#define NN      1536
#define NE      49152
#define EMB     32
#define SLOPE   0.2f
#define CAP     96             // bucket slots per node (P(deg>96) ~ 4e-20)
#define NB_NODE 192            // 192 node blocks * 8 warps = 1536 nodes
#define NB_EDGE 192            // 192 edge blocks * 256 edges = 49152
#define PI_F    3.14159274f
#define TWOPI_F 6.28318548f

// ---------------- device scratch (allocation-free, replay-safe) ----------
__device__ float  g_tar   [NN * 4];        // float4 per node
__device__ float  g_nbr   [NN * 4];        // float4 per node
__device__ float  g_nbrupd[NN * EMB];
__device__ int    g_deg   [NN];            // zeroed at load; k_main resets each run
__device__ float4 g_escB  [NN * CAP];      // {s0,s1,s2, (dst | secA<<16) as float bits}
__device__ float2 g_eaB   [NN * CAP];      // raw edge_attr per slot

// sector tables (rebuilt deterministically every launch by k_tables)
__device__ float2 g_secM [64 * 32];        // [sec][o]: eupd_o = M·ea
__device__ float2 g_secSA[64 * 3];         // [sec][h]
__device__ float2 g_secST[64 * 3];         // [sec][h]
__device__ float  g_bndA [64], g_bndT[64]; // shifted sorted boundaries, [0]=0
__device__ float  g_bnd0A, g_bnd0T;
__device__ int    g_lutA [256], g_lutT[256];

__device__ __forceinline__ float leaky(float x) { return fmaxf(x, SLOPE * x); }

// ================= K0: build sector tables (2 blocks x 1024 thr) =========
// Block 0 = A side (M + SA + bndA + lutA), block 1 = T side (ST + bndT + lutT).
// Produces bit-identical tables to the validated R14 builder.
__global__ __launch_bounds__(1024) void k_tables(
    const float* __restrict__ W_ea, const float* __restrict__ W_et,
    const float* __restrict__ W_att, const float* __restrict__ W_upd)
{
    __shared__ float sWxy[64];     // raw weight pairs of this side
    __shared__ float sAng[64], sBnd[64];
    __shared__ float sUx[64], sUy[64];

    int t = threadIdx.x;
    bool sideA = (blockIdx.x == 0);
    const float* Wside = sideA ? W_ea : W_et;

    if (t < 64) sWxy[t] = Wside[t];
    __syncthreads();

    // boundary angles: sign of w_c·x flips at theta_c +- pi/2
    if (t < 32) {
        float th = atan2f(sWxy[2 * t + 1], sWxy[2 * t]);
        float a0 = th - 1.57079637f; if (a0 < -PI_F) a0 += TWOPI_F;
        float a1 = th + 1.57079637f; if (a1 >  PI_F) a1 -= TWOPI_F;
        sAng[2 * t] = a0; sAng[2 * t + 1] = a1;
    }
    __syncthreads();

    // rank sort (64 threads, 64-iter each)
    if (t < 64) {
        float v = sAng[t];
        int rank = 0;
        for (int q = 0; q < 64; q++) {
            float u = sAng[q];
            rank += (u < v) || (u == v && q < t);
        }
        sBnd[rank] = v;
    }
    __syncthreads();

    float b0 = sBnd[0];
    if (t < 64) {
        float lo = sBnd[t];
        float hi = (t < 63) ? sBnd[t + 1] : sBnd[0] + TWOPI_F;
        float mid = 0.5f * (lo + hi);
        sUx[t] = cosf(mid); sUy[t] = sinf(mid);
        if (sideA) { g_bndA[t] = lo - b0; if (t == 0) g_bnd0A = b0; }
        else       { g_bndT[t] = lo - b0; if (t == 0) g_bnd0T = b0; }
    }
    __syncthreads();

    if (sideA) {
        // M table: thread = sigma*16 + q handles channels o = 2q, 2q+1
        int sigma = t >> 4, q = t & 15;
        float ux = sUx[sigma], uy = sUy[sigma];
        int o0 = 2 * q, o1 = 2 * q + 1;
        float ax0 = 0.f, ay0 = 0.f, ax1 = 0.f, ay1 = 0.f;
        #pragma unroll 8
        for (int c = 0; c < 32; c++) {
            float wx = sWxy[2 * c], wy = sWxy[2 * c + 1];
            float m = (wx * ux + wy * uy >= 0.f) ? 1.f : SLOPE;
            float mx = m * wx, my = m * wy;
            float wu0 = W_upd[o0 * 64 + c], wu1 = W_upd[o1 * 64 + c];
            ax0 += wu0 * mx; ay0 += wu0 * my;
            ax1 += wu1 * mx; ay1 += wu1 * my;
        }
        g_secM[sigma * 32 + o0] = make_float2(ax0, ay0);
        g_secM[sigma * 32 + o1] = make_float2(ax1, ay1);
    }

    // score tables: 192 threads, thread = sigma*3 + h
    if (t < 192) {
        int sigma = t / 3, h = t % 3;
        float ux = sUx[sigma], uy = sUy[sigma];
        int base = sideA ? (h * 128 + 32) : (h * 128 + 64);
        float sx = 0.f, sy = 0.f;
        #pragma unroll 8
        for (int c = 0; c < 32; c++) {
            float wx = sWxy[2 * c], wy = sWxy[2 * c + 1];
            float m = (wx * ux + wy * uy >= 0.f) ? 1.f : SLOPE;
            float wa = W_att[base + c];
            sx += wa * (m * wx); sy += wa * (m * wy);
        }
        if (sideA) g_secSA[t] = make_float2(sx, sy);
        else       g_secST[t] = make_float2(sx, sy);
    }

    // LUT: 256 threads, one bin each
    if (t < 256) {
        float binleft = t * (TWOPI_F / 256.0f);
        int cnt = 0;
        for (int q = 0; q < 64; q++) cnt += ((sBnd[q] - b0) <= binleft);
        if (sideA) g_lutA[t] = cnt - 1; else g_lutT[t] = cnt - 1;
    }
}

// ================= K1: fused node + edge preprocessing (R14 verbatim) =====
__global__ __launch_bounds__(256) void k_prep(
    const float* __restrict__ node_f,
    const float* __restrict__ edge_attr,
    const float* __restrict__ edge_type,
    const float* __restrict__ W_veh,
    const float* __restrict__ W_ped,
    const float* __restrict__ W_att,
    const float* __restrict__ W_upd,
    const int*   __restrict__ src,
    const int*   __restrict__ dst,
    const unsigned int* __restrict__ veh_raw,
    const unsigned int* __restrict__ ped_raw)
{
    __shared__ __align__(16) float sW[3 * 1024 + 384];
    int tid = threadIdx.x, lane = tid & 31, w = tid >> 5;

    if (blockIdx.x < NB_NODE) {
        // ---------- node part: warp per node (8 per block) ----------
        __shared__ int s_notInt, s_notF32;
        if (tid == 0) { s_notInt = 0; s_notF32 = 0; }
        __syncthreads();
        for (int idx = tid; idx < 384; idx += 256) {
            unsigned int x = veh_raw[idx];
            if (!(x == 0u || x == 1u))          atomicOr(&s_notInt, 1);
            if (!(x == 0u || x == 0x3F800000u)) atomicOr(&s_notF32, 1);
        }
        float* sWv  = sW;
        float* sWp  = sW + 1024;
        float* sWun = sW + 2048;
        float* sWatt= sW + 3072;
        for (int idx = tid; idx < 1024; idx += 256) {
            int o = idx >> 5, c = idx & 31;
            sWv [c * 32 + o] = W_veh[idx];
            sWp [c * 32 + o] = W_ped[idx];
            sWun[c * 32 + o] = W_upd[o * 64 + 32 + c];
        }
        for (int idx = tid; idx < 384; idx += 256) sWatt[idx] = W_att[idx];
        __syncthreads();
        int dtype = (!s_notInt) ? 0 : ((!s_notF32) ? 1 : 2);

        int i = blockIdx.x * 8 + w;
        float f = node_f[i * 32 + lane];
        int v, p;
        if (dtype == 0)      { v = ((const int*)  veh_raw)[i] != 0;   p = ((const int*)  ped_raw)[i] != 0; }
        else if (dtype == 1) { v = ((const float*)veh_raw)[i] != 0.f; p = ((const float*)ped_raw)[i] != 0.f; }
        else                 { v = ((const unsigned char*)veh_raw)[i] != 0;
                               p = ((const unsigned char*)ped_raw)[i] != 0; }

        const float* Wt = p ? sWp : sWv;
        float acc = 0.f;
        #pragma unroll
        for (int c = 0; c < 32; c++)
            acc += __shfl_sync(0xffffffffu, f, c) * Wt[c * 32 + lane];
        float emb = (p || v) ? acc : 0.f;
        emb = leaky(emb);

        float t0 = emb * sWatt[lane],      t1 = emb * sWatt[128 + lane], t2 = emb * sWatt[256 + lane];
        float b0 = emb * sWatt[96 + lane], b1 = emb * sWatt[224 + lane], b2 = emb * sWatt[352 + lane];
        #pragma unroll
        for (int off = 16; off; off >>= 1) {
            t0 += __shfl_xor_sync(0xffffffffu, t0, off);
            t1 += __shfl_xor_sync(0xffffffffu, t1, off);
            t2 += __shfl_xor_sync(0xffffffffu, t2, off);
            b0 += __shfl_xor_sync(0xffffffffu, b0, off);
            b1 += __shfl_xor_sync(0xffffffffu, b1, off);
            b2 += __shfl_xor_sync(0xffffffffu, b2, off);
        }
        if (lane == 0) {
            ((float4*)g_tar)[i] = make_float4(t0, t1, t2, 0.f);
            ((float4*)g_nbr)[i] = make_float4(b0, b1, b2, 0.f);
        }
        float u = 0.f;
        #pragma unroll
        for (int c = 0; c < 32; c++)
            u += __shfl_sync(0xffffffffu, emb, c) * sWun[c * 32 + lane];
        g_nbrupd[i * 32 + lane] = u;
    } else {
        // ---------- edge part: thread = edge, sector-table scores ----------
        float2* sSA2 = (float2*)sW;              // 192 float2
        float2* sST2 = (float2*)(sW + 384);      // 192 float2
        float*  sBndA = sW + 768;                // 64
        float*  sBndT = sW + 832;                // 64
        int*    sLutA = (int*)(sW + 896);        // 256
        int*    sLutT = (int*)(sW + 1152);       // 256
        if (tid < 192) { sSA2[tid] = g_secSA[tid]; sST2[tid] = g_secST[tid]; }
        if (tid < 64)  { sBndA[tid] = g_bndA[tid]; sBndT[tid] = g_bndT[tid]; }
        sLutA[tid] = g_lutA[tid];
        sLutT[tid] = g_lutT[tid];
        float bnd0A = g_bnd0A, bnd0T = g_bnd0T;
        __syncthreads();

        int e = (blockIdx.x - NB_NODE) * 256 + tid;
        float2 ea = ((const float2*)edge_attr)[e];
        float2 et = ((const float2*)edge_type)[e];
        int sn = src[e], dn = dst[e];

        float psiA = atan2f(ea.y, ea.x) - bnd0A; if (psiA < 0.f) psiA += TWOPI_F;
        int binA = min((int)(psiA * (256.0f / TWOPI_F)), 255);
        int sa = sLutA[binA];
        while (sa < 63 && sBndA[sa + 1] <= psiA) sa++;

        float psiT = atan2f(et.y, et.x) - bnd0T; if (psiT < 0.f) psiT += TWOPI_F;
        int binT = min((int)(psiT * (256.0f / TWOPI_F)), 255);
        int st = sLutT[binT];
        while (st < 63 && sBndT[st + 1] <= psiT) st++;

        float2 A0 = sSA2[sa * 3], A1 = sSA2[sa * 3 + 1], A2 = sSA2[sa * 3 + 2];
        float2 T0 = sST2[st * 3], T1 = sST2[st * 3 + 1], T2 = sST2[st * 3 + 2];
        float s0 = A0.x * ea.x + A0.y * ea.y + T0.x * et.x + T0.y * et.y;
        float s1 = A1.x * ea.x + A1.y * ea.y + T1.x * et.x + T1.y * et.y;
        float s2 = A2.x * ea.x + A2.y * ea.y + T2.x * et.x + T2.y * et.y;

        int pos = atomicAdd(&g_deg[sn], 1);
        if (pos < CAP) {
            int slot = sn * CAP + pos;
            g_escB[slot] = make_float4(s0, s1, s2, __int_as_float(dn | (sa << 16)));
            g_eaB[slot] = ea;
        }
    }
}

// ================= K2: block-per-node attention + aggregation (R14) =======
__global__ __launch_bounds__(128) void k_main(float* __restrict__ out) {
    __shared__ int    sDst[CAP];
    __shared__ int    sSig[CAP];
    __shared__ float2 sEa [CAP];
    __shared__ float  sAtt[CAP * 3];
    __shared__ int    sMw [CAP];
    __shared__ int    sHash[256];
    __shared__ int    sNp;
    __shared__ float  sSum[12];
    __shared__ float  sPart[12 * 32];
    __shared__ __align__(16) float sU[CAP * 32];

    int i = blockIdx.x;
    int tid = threadIdx.x, lane = tid & 31, w = tid >> 5;

    int d = min(g_deg[i], CAP);
    float4 ti = ((const float4*)g_tar)[i];

    if (d == 0) {
        float acc = 0.f;
        for (int j = w; j < NN; j += 4) acc += leaky(g_nbrupd[j * 32 + lane]);
        sPart[w * 32 + lane] = acc;
        __syncthreads();
        if (tid < 96) {
            int o = tid & 31;
            out[i * 96 + tid] = (sPart[o] + sPart[32 + o] + sPart[64 + o] + sPart[96 + o]) * (1.f / NN);
        }
        return;
    }

    sHash[tid] = -1; sHash[tid + 128] = -1;
    if (tid == 0) sNp = 0;
    for (int idx = tid; idx < d * 8; idx += 128) ((float4*)sU)[idx] = make_float4(0.f, 0.f, 0.f, 0.f);

    int grp = tid & 3;
    int k = (tid >> 2) + (grp << 5);
    bool act = (grp < 3) && (k < d);

    // pass 1: load edge records
    int dk = 0;
    float4 nb = make_float4(0.f, 0.f, 0.f, 0.f);
    if (act) {
        float4 sc = g_escB[i * CAP + k];
        int packed = __float_as_int(sc.w);
        dk = packed & 0xFFFF;
        sDst[k] = dk;
        sSig[k] = packed >> 16;
        sEa[k] = g_eaB[i * CAP + k];
        sAtt[k * 3]     = sc.x;
        sAtt[k * 3 + 1] = sc.y;
        sAtt[k * 3 + 2] = sc.z;
        nb = ((const float4*)g_nbr)[dk];
    }
    __syncthreads();
    if (tid == 0) g_deg[i] = 0;   // reset for next graph replay

    // pass 2: hash dedupe; dupes merge scores into root, zero own
    int leader = k;
    if (act) {
        unsigned h = ((unsigned)dk * 2654435761u) >> 24;
        while (true) {
            int old = atomicCAS(&sHash[h], -1, k);
            if (old == -1) break;
            if (sDst[old] == dk) { leader = old; break; }
            h = (h + 1) & 255;
        }
        sMw[k] = leader;
        if (leader != k) {
            atomicAdd(&sAtt[leader * 3 + 0], sAtt[k * 3 + 0]);
            atomicAdd(&sAtt[leader * 3 + 1], sAtt[k * 3 + 1]);
            atomicAdd(&sAtt[leader * 3 + 2], sAtt[k * 3 + 2]);
            sAtt[k * 3] = 0.f; sAtt[k * 3 + 1] = 0.f; sAtt[k * 3 + 2] = 0.f;
            atomicAdd(&sNp, 1);
        }
    }
    __syncthreads();

    // pass 3: finalize + exp (roots); dupes/inactive contribute 0
    float e0 = 0.f, e1 = 0.f, e2 = 0.f;
    if (act && leader == k) {
        e0 = __expf(leaky(ti.x + sAtt[k * 3]     + nb.x));
        e1 = __expf(leaky(ti.y + sAtt[k * 3 + 1] + nb.y));
        e2 = __expf(leaky(ti.z + sAtt[k * 3 + 2] + nb.z));
        sAtt[k * 3] = e0; sAtt[k * 3 + 1] = e1; sAtt[k * 3 + 2] = e2;
    } else if (act) {
        sAtt[k * 3] = 0.f; sAtt[k * 3 + 1] = 0.f; sAtt[k * 3 + 2] = 0.f;
    }
    float S0 = e0, S1 = e1, S2 = e2;
    #pragma unroll
    for (int off = 16; off; off >>= 1) {
        S0 += __shfl_xor_sync(0xffffffffu, S0, off);
        S1 += __shfl_xor_sync(0xffffffffu, S1, off);
        S2 += __shfl_xor_sync(0xffffffffu, S2, off);
    }
    if (lane == 0) { sSum[w * 3] = S0; sSum[w * 3 + 1] = S1; sSum[w * 3 + 2] = S2; }
    __syncthreads();
    float inv0 = 1.f / (sSum[0] + sSum[3] + sSum[6] + sSum[9]);
    float inv1 = 1.f / (sSum[1] + sSum[4] + sSum[7] + sSum[10]);
    float inv2 = 1.f / (sSum[2] + sSum[5] + sSum[8] + sSum[11]);
    int np = sNp;

    // phase B: on-the-fly eupd = M_sec . ea (dupes have weight 0)
    float a0 = 0.f, a1 = 0.f, a2 = 0.f;
    if (np == 0) {
        #pragma unroll 4
        for (int j = w; j < d; j += 4) {
            float2 m = g_secM[sSig[j] * 32 + lane];   // lane-coalesced
            float2 eaj = sEa[j];
            float u = m.x * eaj.x + m.y * eaj.y;
            float v = leaky(u + g_nbrupd[sDst[j] * 32 + lane]);
            a0 += sAtt[j * 3] * v; a1 += sAtt[j * 3 + 1] * v; a2 += sAtt[j * 3 + 2] * v;
        }
    } else {
        for (int j = w; j < d; j += 4) {
            float2 m = g_secM[sSig[j] * 32 + lane];
            float2 eaj = sEa[j];
            atomicAdd(&sU[sMw[j] * 32 + lane], m.x * eaj.x + m.y * eaj.y);
        }
        __syncthreads();
        for (int j = w; j < d; j += 4) {
            float v = leaky(sU[j * 32 + lane] + g_nbrupd[sDst[j] * 32 + lane]);
            a0 += sAtt[j * 3] * v; a1 += sAtt[j * 3 + 1] * v; a2 += sAtt[j * 3 + 2] * v;
        }
    }
    sPart[(w * 3 + 0) * 32 + lane] = a0;
    sPart[(w * 3 + 1) * 32 + lane] = a1;
    sPart[(w * 3 + 2) * 32 + lane] = a2;
    __syncthreads();
    if (tid < 96) {
        int h = tid / 32, o = tid % 32;
        float inv = (h == 0) ? inv0 : ((h == 1) ? inv1 : inv2);
        out[i * 96 + h * 32 + o] =
            (sPart[(0 + h) * 32 + o] + sPart[(3 + h) * 32 + o]
           + sPart[(6 + h) * 32 + o] + sPart[(9 + h) * 32 + o]) * inv;
    }
}

// ---------------- launch ----------------
extern "C" void kernel_launch(void* const* d_in, const int* in_sizes, int n_in,
                              void* d_out, int out_size) {
    const float* node_f    = (const float*)d_in[0];
    const float* edge_attr = (const float*)d_in[1];
    const float* edge_type = (const float*)d_in[2];
    const float* W_veh     = (const float*)d_in[3];
    const float* W_ped     = (const float*)d_in[4];
    const float* W_ea      = (const float*)d_in[5];
    const float* W_et      = (const float*)d_in[6];
    const float* W_att     = (const float*)d_in[7];
    const float* W_upd     = (const float*)d_in[8];
    const int*   edge_index= (const int*)  d_in[9];
    const unsigned int* veh = (const unsigned int*)d_in[10];
    const unsigned int* ped = (const unsigned int*)d_in[11];

    const int* src = edge_index;        // edge_index[0, :]
    const int* dst = edge_index + NE;   // edge_index[1, :]
    float* out = (float*)d_out;

    k_tables<<<2, 1024>>>(W_ea, W_et, W_att, W_upd);
    k_prep<<<NB_NODE + NB_EDGE, 256>>>(node_f, edge_attr, edge_type,
                                       W_veh, W_ped, W_att, W_upd,
                                       src, dst, veh, ped);
    k_main<<<NN, 128>>>(out);
}

// round 16
// speedup vs baseline: 1.7019x; 1.7019x over previous
#include <cuda_runtime.h>

// ---------------- problem constants ----------------
#define NN      1536
#define NE      49152
#define EMB     32
#define SLOPE   0.2f
#define CAP     96             // bucket slots per node (P(deg>96) ~ 4e-20)
#define NB_NODE 192            // 192 node blocks * 8 warps = 1536 nodes
#define NB_EDGE 192            // 192 edge blocks * 256 edges = 49152
#define PI_F    3.14159274f
#define TWOPI_F 6.28318548f

// ---------------- device scratch (allocation-free, replay-safe) ----------
__device__ float  g_tar   [NN * 4];        // float4 per node
__device__ float  g_nbr   [NN * 4];        // float4 per node
__device__ float  g_nbrupd[NN * EMB];
__device__ int    g_deg   [NN];            // zeroed at load; k_main resets each run
__device__ float4 g_escB  [NN * CAP];      // {s0,s1,s2, (dst | secA<<16) as float bits}
__device__ float2 g_eaB   [NN * CAP];      // raw edge_attr per slot
__device__ float2 g_secM  [64 * 32];       // [sec][o]: eupd_o = M·ea (built by node blocks)

__device__ __forceinline__ float leaky(float x) { return fmaxf(x, SLOPE * x); }

// ================= K1: fused node + edge preprocessing + table build ======
__global__ __launch_bounds__(256) void k_prep(
    const float* __restrict__ node_f,
    const float* __restrict__ edge_attr,
    const float* __restrict__ edge_type,
    const float* __restrict__ W_veh,
    const float* __restrict__ W_ped,
    const float* __restrict__ W_ea,
    const float* __restrict__ W_et,
    const float* __restrict__ W_att,
    const float* __restrict__ W_upd,
    const int*   __restrict__ src,
    const int*   __restrict__ dst,
    const unsigned int* __restrict__ veh_raw,
    const unsigned int* __restrict__ ped_raw)
{
    __shared__ __align__(16) float sW[3 * 1024 + 384];
    int tid = threadIdx.x, lane = tid & 31, w = tid >> 5;

    if (blockIdx.x < NB_NODE) {
        // ---------- node part: warp per node (8 per block) ----------
        __shared__ int s_notInt, s_notF32;
        __shared__ float sWea2[64], sAng[64], sBnd[64];
        if (tid == 0) { s_notInt = 0; s_notF32 = 0; }
        __syncthreads();
        for (int idx = tid; idx < 384; idx += 256) {   // dtype sniff (min buf = 384 words)
            unsigned int x = veh_raw[idx];
            if (!(x == 0u || x == 1u))          atomicOr(&s_notInt, 1);
            if (!(x == 0u || x == 0x3F800000u)) atomicOr(&s_notF32, 1);
        }
        float* sWv  = sW;
        float* sWp  = sW + 1024;
        float* sWun = sW + 2048;
        float* sWatt= sW + 3072;
        for (int idx = tid; idx < 1024; idx += 256) {
            int o = idx >> 5, c = idx & 31;
            sWv [c * 32 + o] = W_veh[idx];
            sWp [c * 32 + o] = W_ped[idx];
            sWun[c * 32 + o] = W_upd[o * 64 + 32 + c];
        }
        for (int idx = tid; idx < 384; idx += 256) sWatt[idx] = W_att[idx];
        if (tid < 64) sWea2[tid] = W_ea[tid];
        __syncthreads();
        int dtype = (!s_notInt) ? 0 : ((!s_notF32) ? 1 : 2);

        int i = blockIdx.x * 8 + w;
        float f = node_f[i * 32 + lane];
        int v, p;
        if (dtype == 0)      { v = ((const int*)  veh_raw)[i] != 0;   p = ((const int*)  ped_raw)[i] != 0; }
        else if (dtype == 1) { v = ((const float*)veh_raw)[i] != 0.f; p = ((const float*)ped_raw)[i] != 0.f; }
        else                 { v = ((const unsigned char*)veh_raw)[i] != 0;
                               p = ((const unsigned char*)ped_raw)[i] != 0; }

        const float* Wt = p ? sWp : sWv;
        float acc = 0.f;
        #pragma unroll
        for (int c = 0; c < 32; c++)
            acc += __shfl_sync(0xffffffffu, f, c) * Wt[c * 32 + lane];
        float emb = (p || v) ? acc : 0.f;
        emb = leaky(emb);

        float t0 = emb * sWatt[lane],      t1 = emb * sWatt[128 + lane], t2 = emb * sWatt[256 + lane];
        float b0 = emb * sWatt[96 + lane], b1 = emb * sWatt[224 + lane], b2 = emb * sWatt[352 + lane];
        #pragma unroll
        for (int off = 16; off; off >>= 1) {
            t0 += __shfl_xor_sync(0xffffffffu, t0, off);
            t1 += __shfl_xor_sync(0xffffffffu, t1, off);
            t2 += __shfl_xor_sync(0xffffffffu, t2, off);
            b0 += __shfl_xor_sync(0xffffffffu, b0, off);
            b1 += __shfl_xor_sync(0xffffffffu, b1, off);
            b2 += __shfl_xor_sync(0xffffffffu, b2, off);
        }
        if (lane == 0) {
            ((float4*)g_tar)[i] = make_float4(t0, t1, t2, 0.f);
            ((float4*)g_nbr)[i] = make_float4(b0, b1, b2, 0.f);
        }
        float u = 0.f;
        #pragma unroll
        for (int c = 0; c < 32; c++)
            u += __shfl_sync(0xffffffffu, emb, c) * sWun[c * 32 + lane];
        g_nbrupd[i * 32 + lane] = u;

        // ---------- M-table slice build (entries b*11 .. b*11+10) ----------
        __syncthreads();
        if (tid < 32) {
            float th = atan2f(sWea2[2 * tid + 1], sWea2[2 * tid]);
            float a0 = th - 1.57079637f; if (a0 < -PI_F) a0 += TWOPI_F;
            float a1 = th + 1.57079637f; if (a1 >  PI_F) a1 -= TWOPI_F;
            sAng[2 * tid] = a0; sAng[2 * tid + 1] = a1;
        }
        __syncthreads();
        if (tid < 64) {
            float vv = sAng[tid];
            int rank = 0;
            for (int q = 0; q < 64; q++) {
                float uu = sAng[q];
                rank += (uu < vv) || (uu == vv && q < tid);
            }
            sBnd[rank] = vv;
        }
        __syncthreads();
        if (tid < 11) {
            int g = blockIdx.x * 11 + tid;
            if (g < 2048) {
                int sigma = g >> 5, o = g & 31;
                float lo = sBnd[sigma];
                float hi = (sigma < 63) ? sBnd[sigma + 1] : sBnd[0] + TWOPI_F;
                float mid = 0.5f * (lo + hi);
                float ux = cosf(mid), uy = sinf(mid);
                float ax = 0.f, ay = 0.f;
                #pragma unroll 8
                for (int c = 0; c < 32; c++) {
                    float wx = sWea2[2 * c], wy = sWea2[2 * c + 1];
                    float m = (wx * ux + wy * uy >= 0.f) ? 1.f : SLOPE;
                    float wu = W_upd[o * 64 + c];
                    ax += wu * (m * wx); ay += wu * (m * wy);
                }
                g_secM[g] = make_float2(ax, ay);
            }
        }
    } else {
        // ---------- edge part: build score tables in smem, then 256 edges --
        __shared__ float sWea[64], sWet[64];
        __shared__ float sAngA[64], sAngT[64];
        __shared__ float sBndA[64], sBndT[64];     // raw sorted
        __shared__ float sShA[64], sShT[64];       // shifted (bnd - b0)
        __shared__ float2 sSA2[192], sST2[192];    // [sec][h]
        __shared__ int   sLutA[256], sLutT[256];

        if (tid < 64) sWea[tid] = W_ea[tid];
        else if (tid < 128) sWet[tid - 64] = W_et[tid - 64];
        __syncthreads();

        if (tid < 32) {
            float th = atan2f(sWea[2 * tid + 1], sWea[2 * tid]);
            float a0 = th - 1.57079637f; if (a0 < -PI_F) a0 += TWOPI_F;
            float a1 = th + 1.57079637f; if (a1 >  PI_F) a1 -= TWOPI_F;
            sAngA[2 * tid] = a0; sAngA[2 * tid + 1] = a1;
        } else if (tid < 64) {
            int c = tid - 32;
            float th = atan2f(sWet[2 * c + 1], sWet[2 * c]);
            float a0 = th - 1.57079637f; if (a0 < -PI_F) a0 += TWOPI_F;
            float a1 = th + 1.57079637f; if (a1 >  PI_F) a1 -= TWOPI_F;
            sAngT[2 * c] = a0; sAngT[2 * c + 1] = a1;
        }
        __syncthreads();

        if (tid < 64) {
            float vv = sAngA[tid];
            int rank = 0;
            for (int q = 0; q < 64; q++) {
                float uu = sAngA[q];
                rank += (uu < vv) || (uu == vv && q < tid);
            }
            sBndA[rank] = vv;
        } else if (tid < 128) {
            int j = tid - 64;
            float vv = sAngT[j];
            int rank = 0;
            for (int q = 0; q < 64; q++) {
                float uu = sAngT[q];
                rank += (uu < vv) || (uu == vv && q < j);
            }
            sBndT[rank] = vv;
        }
        __syncthreads();

        float b0A = sBndA[0], b0T = sBndT[0];
        if (tid < 64) sShA[tid] = sBndA[tid] - b0A;
        else if (tid < 128) sShT[tid - 64] = sBndT[tid - 64] - b0T;
        if (tid < 192) {
            int sigma = tid / 3, h = tid % 3;
            // A side
            {
                float lo = sBndA[sigma];
                float hi = (sigma < 63) ? sBndA[sigma + 1] : sBndA[0] + TWOPI_F;
                float mid = 0.5f * (lo + hi);
                float ux = cosf(mid), uy = sinf(mid);
                float sx = 0.f, sy = 0.f;
                #pragma unroll 8
                for (int c = 0; c < 32; c++) {
                    float wx = sWea[2 * c], wy = sWea[2 * c + 1];
                    float m = (wx * ux + wy * uy >= 0.f) ? 1.f : SLOPE;
                    float wa = W_att[h * 128 + 32 + c];
                    sx += wa * (m * wx); sy += wa * (m * wy);
                }
                sSA2[tid] = make_float2(sx, sy);
            }
            // T side
            {
                float lo = sBndT[sigma];
                float hi = (sigma < 63) ? sBndT[sigma + 1] : sBndT[0] + TWOPI_F;
                float mid = 0.5f * (lo + hi);
                float ux = cosf(mid), uy = sinf(mid);
                float sx = 0.f, sy = 0.f;
                #pragma unroll 8
                for (int c = 0; c < 32; c++) {
                    float wx = sWet[2 * c], wy = sWet[2 * c + 1];
                    float m = (wx * ux + wy * uy >= 0.f) ? 1.f : SLOPE;
                    float wa = W_att[h * 128 + 64 + c];
                    sx += wa * (m * wx); sy += wa * (m * wy);
                }
                sST2[tid] = make_float2(sx, sy);
            }
        }
        {   // LUTs: one bin per thread, counting raw boundaries shifted by b0
            float binleft = tid * (TWOPI_F / 256.0f);
            int cntA = 0, cntT = 0;
            for (int q = 0; q < 64; q++) {
                cntA += ((sBndA[q] - b0A) <= binleft);
                cntT += ((sBndT[q] - b0T) <= binleft);
            }
            sLutA[tid] = cntA - 1;
            sLutT[tid] = cntT - 1;
        }
        __syncthreads();

        // ---------- per-thread edge processing ----------
        int e = (blockIdx.x - NB_NODE) * 256 + tid;
        float2 ea = ((const float2*)edge_attr)[e];
        float2 et = ((const float2*)edge_type)[e];
        int sn = src[e], dn = dst[e];

        float psiA = atan2f(ea.y, ea.x) - b0A; if (psiA < 0.f) psiA += TWOPI_F;
        int binA = min((int)(psiA * (256.0f / TWOPI_F)), 255);
        int sa = sLutA[binA];
        while (sa < 63 && sShA[sa + 1] <= psiA) sa++;

        float psiT = atan2f(et.y, et.x) - b0T; if (psiT < 0.f) psiT += TWOPI_F;
        int binT = min((int)(psiT * (256.0f / TWOPI_F)), 255);
        int st = sLutT[binT];
        while (st < 63 && sShT[st + 1] <= psiT) st++;

        float2 A0 = sSA2[sa * 3], A1 = sSA2[sa * 3 + 1], A2 = sSA2[sa * 3 + 2];
        float2 T0 = sST2[st * 3], T1 = sST2[st * 3 + 1], T2 = sST2[st * 3 + 2];
        float s0 = A0.x * ea.x + A0.y * ea.y + T0.x * et.x + T0.y * et.y;
        float s1 = A1.x * ea.x + A1.y * ea.y + T1.x * et.x + T1.y * et.y;
        float s2 = A2.x * ea.x + A2.y * ea.y + T2.x * et.x + T2.y * et.y;

        int pos = atomicAdd(&g_deg[sn], 1);
        if (pos < CAP) {
            int slot = sn * CAP + pos;
            g_escB[slot] = make_float4(s0, s1, s2, __int_as_float(dn | (sa << 16)));
            g_eaB[slot] = ea;
        }
    }
}

// ================= K2: block-per-node attention + aggregation (R14) =======
__global__ __launch_bounds__(128) void k_main(float* __restrict__ out) {
    __shared__ int    sDst[CAP];
    __shared__ int    sSig[CAP];
    __shared__ float2 sEa [CAP];
    __shared__ float  sAtt[CAP * 3];
    __shared__ int    sMw [CAP];
    __shared__ int    sHash[256];
    __shared__ int    sNp;
    __shared__ float  sSum[12];
    __shared__ float  sPart[12 * 32];
    __shared__ __align__(16) float sU[CAP * 32];

    int i = blockIdx.x;
    int tid = threadIdx.x, lane = tid & 31, w = tid >> 5;

    int d = min(g_deg[i], CAP);
    float4 ti = ((const float4*)g_tar)[i];

    if (d == 0) {
        float acc = 0.f;
        for (int j = w; j < NN; j += 4) acc += leaky(g_nbrupd[j * 32 + lane]);
        sPart[w * 32 + lane] = acc;
        __syncthreads();
        if (tid < 96) {
            int o = tid & 31;
            out[i * 96 + tid] = (sPart[o] + sPart[32 + o] + sPart[64 + o] + sPart[96 + o]) * (1.f / NN);
        }
        return;
    }

    sHash[tid] = -1; sHash[tid + 128] = -1;
    if (tid == 0) sNp = 0;
    for (int idx = tid; idx < d * 8; idx += 128) ((float4*)sU)[idx] = make_float4(0.f, 0.f, 0.f, 0.f);

    int grp = tid & 3;
    int k = (tid >> 2) + (grp << 5);
    bool act = (grp < 3) && (k < d);

    // pass 1: load edge records
    int dk = 0;
    float4 nb = make_float4(0.f, 0.f, 0.f, 0.f);
    if (act) {
        float4 sc = g_escB[i * CAP + k];
        int packed = __float_as_int(sc.w);
        dk = packed & 0xFFFF;
        sDst[k] = dk;
        sSig[k] = packed >> 16;
        sEa[k] = g_eaB[i * CAP + k];
        sAtt[k * 3]     = sc.x;
        sAtt[k * 3 + 1] = sc.y;
        sAtt[k * 3 + 2] = sc.z;
        nb = ((const float4*)g_nbr)[dk];
    }
    __syncthreads();
    if (tid == 0) g_deg[i] = 0;   // reset for next graph replay

    // pass 2: hash dedupe; dupes merge scores into root, zero own
    int leader = k;
    if (act) {
        unsigned h = ((unsigned)dk * 2654435761u) >> 24;
        while (true) {
            int old = atomicCAS(&sHash[h], -1, k);
            if (old == -1) break;
            if (sDst[old] == dk) { leader = old; break; }
            h = (h + 1) & 255;
        }
        sMw[k] = leader;
        if (leader != k) {
            atomicAdd(&sAtt[leader * 3 + 0], sAtt[k * 3 + 0]);
            atomicAdd(&sAtt[leader * 3 + 1], sAtt[k * 3 + 1]);
            atomicAdd(&sAtt[leader * 3 + 2], sAtt[k * 3 + 2]);
            sAtt[k * 3] = 0.f; sAtt[k * 3 + 1] = 0.f; sAtt[k * 3 + 2] = 0.f;
            atomicAdd(&sNp, 1);
        }
    }
    __syncthreads();

    // pass 3: finalize + exp (roots); dupes/inactive contribute 0
    float e0 = 0.f, e1 = 0.f, e2 = 0.f;
    if (act && leader == k) {
        e0 = __expf(leaky(ti.x + sAtt[k * 3]     + nb.x));
        e1 = __expf(leaky(ti.y + sAtt[k * 3 + 1] + nb.y));
        e2 = __expf(leaky(ti.z + sAtt[k * 3 + 2] + nb.z));
        sAtt[k * 3] = e0; sAtt[k * 3 + 1] = e1; sAtt[k * 3 + 2] = e2;
    } else if (act) {
        sAtt[k * 3] = 0.f; sAtt[k * 3 + 1] = 0.f; sAtt[k * 3 + 2] = 0.f;
    }
    float S0 = e0, S1 = e1, S2 = e2;
    #pragma unroll
    for (int off = 16; off; off >>= 1) {
        S0 += __shfl_xor_sync(0xffffffffu, S0, off);
        S1 += __shfl_xor_sync(0xffffffffu, S1, off);
        S2 += __shfl_xor_sync(0xffffffffu, S2, off);
    }
    if (lane == 0) { sSum[w * 3] = S0; sSum[w * 3 + 1] = S1; sSum[w * 3 + 2] = S2; }
    __syncthreads();
    float inv0 = 1.f / (sSum[0] + sSum[3] + sSum[6] + sSum[9]);
    float inv1 = 1.f / (sSum[1] + sSum[4] + sSum[7] + sSum[10]);
    float inv2 = 1.f / (sSum[2] + sSum[5] + sSum[8] + sSum[11]);
    int np = sNp;

    // phase B: on-the-fly eupd = M_sec . ea (dupes have weight 0)
    float a0 = 0.f, a1 = 0.f, a2 = 0.f;
    if (np == 0) {
        #pragma unroll 4
        for (int j = w; j < d; j += 4) {
            float2 m = g_secM[sSig[j] * 32 + lane];   // lane-coalesced
            float2 eaj = sEa[j];
            float u = m.x * eaj.x + m.y * eaj.y;
            float v = leaky(u + g_nbrupd[sDst[j] * 32 + lane]);
            a0 += sAtt[j * 3] * v; a1 += sAtt[j * 3 + 1] * v; a2 += sAtt[j * 3 + 2] * v;
        }
    } else {
        for (int j = w; j < d; j += 4) {
            float2 m = g_secM[sSig[j] * 32 + lane];
            float2 eaj = sEa[j];
            atomicAdd(&sU[sMw[j] * 32 + lane], m.x * eaj.x + m.y * eaj.y);
        }
        __syncthreads();
        for (int j = w; j < d; j += 4) {
            float v = leaky(sU[j * 32 + lane] + g_nbrupd[sDst[j] * 32 + lane]);
            a0 += sAtt[j * 3] * v; a1 += sAtt[j * 3 + 1] * v; a2 += sAtt[j * 3 + 2] * v;
        }
    }
    sPart[(w * 3 + 0) * 32 + lane] = a0;
    sPart[(w * 3 + 1) * 32 + lane] = a1;
    sPart[(w * 3 + 2) * 32 + lane] = a2;
    __syncthreads();
    if (tid < 96) {
        int h = tid / 32, o = tid % 32;
        float inv = (h == 0) ? inv0 : ((h == 1) ? inv1 : inv2);
        out[i * 96 + h * 32 + o] =
            (sPart[(0 + h) * 32 + o] + sPart[(3 + h) * 32 + o]
           + sPart[(6 + h) * 32 + o] + sPart[(9 + h) * 32 + o]) * inv;
    }
}

// ---------------- launch ----------------
extern "C" void kernel_launch(void* const* d_in, const int* in_sizes, int n_in,
                              void* d_out, int out_size) {
    const float* node_f    = (const float*)d_in[0];
    const float* edge_attr = (const float*)d_in[1];
    const float* edge_type = (const float*)d_in[2];
    const float* W_veh     = (const float*)d_in[3];
    const float* W_ped     = (const float*)d_in[4];
    const float* W_ea      = (const float*)d_in[5];
    const float* W_et      = (const float*)d_in[6];
    const float* W_att     = (const float*)d_in[7];
    const float* W_upd     = (const float*)d_in[8];
    const int*   edge_index= (const int*)  d_in[9];
    const unsigned int* veh = (const unsigned int*)d_in[10];
    const unsigned int* ped = (const unsigned int*)d_in[11];

    const int* src = edge_index;        // edge_index[0, :]
    const int* dst = edge_index + NE;   // edge_index[1, :]
    float* out = (float*)d_out;

    k_prep<<<NB_NODE + NB_EDGE, 256>>>(node_f, edge_attr, edge_type,
                                       W_veh, W_ped, W_ea, W_et, W_att, W_upd,
                                       src, dst, veh, ped);
    k_main<<<NN, 128>>>(out);
}